// round 8
// baseline (speedup 1.0000x reference)
#include <cuda_runtime.h>
#include <cuda_bf16.h>
#include <math.h>
#include <stdint.h>

#define BN 4
#define HH 128
#define WW 128
#define HWS (HH * WW)
#define CC 64
#define O1 64
#define O2 32
#define NOFF 27
#define NPIX (BN * HWS)
#define TP 128
#define ST 72              // smem row stride in bf16 elems (144B)
#define STB 144

// deform kernel smem offsets
#define SM_AH   0
#define SM_AL   18432
#define SM_BH   36864
#define SM_BL   46080
#define SM_SWT  55296
#define SM_SIDX 57344
#define SM_TOTAL 59392

// offconv smem offsets (N=32)
#define OC_AH   0
#define OC_AL   18432
#define OC_BH   36864
#define OC_BL   41472
#define OC_TOT  46080

// ---------------- device scratch ----------------
__device__ float g_x1t[BN * HWS * CC];    // NHWC layer-1 input
__device__ float g_x2t[BN * HWS * CC];    // NHWC layer-1 output
__device__ float g_off[BN * NOFF * HWS];
__device__ __nv_bfloat16 g_w1h[9 * O1 * CC];
__device__ __nv_bfloat16 g_w1l[9 * O1 * CC];
__device__ __nv_bfloat16 g_w2h[9 * O2 * CC];
__device__ __nv_bfloat16 g_w2l[9 * O2 * CC];
__device__ __nv_bfloat16 g_o1h[9 * O2 * CC];
__device__ __nv_bfloat16 g_o1l[9 * O2 * CC];
__device__ __nv_bfloat16 g_o2h[9 * O2 * CC];
__device__ __nv_bfloat16 g_o2l[9 * O2 * CC];
__device__ float g_b1[O1];
__device__ float g_b2[O2];

// ---------------- helpers ----------------
__device__ __forceinline__ unsigned smem_u32(const void* p) {
    unsigned a;
    asm("{ .reg .u64 t; cvta.to.shared.u64 t, %1; cvt.u32.u64 %0, t; }" : "=r"(a) : "l"(p));
    return a;
}
__device__ __forceinline__ void ldsm4(unsigned* r, unsigned addr) {
    asm volatile("ldmatrix.sync.aligned.m8n8.x4.shared.b16 {%0,%1,%2,%3}, [%4];"
                 : "=r"(r[0]), "=r"(r[1]), "=r"(r[2]), "=r"(r[3]) : "r"(addr));
}
__device__ __forceinline__ void mma16816(float* c, const unsigned* a, unsigned b0, unsigned b1) {
    asm volatile(
        "mma.sync.aligned.m16n8k16.row.col.f32.bf16.bf16.f32 "
        "{%0,%1,%2,%3}, {%4,%5,%6,%7}, {%8,%9}, {%0,%1,%2,%3};"
        : "+f"(c[0]), "+f"(c[1]), "+f"(c[2]), "+f"(c[3])
        : "r"(a[0]), "r"(a[1]), "r"(a[2]), "r"(a[3]), "r"(b0), "r"(b1));
}
__device__ __forceinline__ unsigned bf16x2_rn(float lo, float hi) {
    unsigned r;
    asm("cvt.rn.bf16x2.f32 %0, %1, %2;" : "=r"(r) : "f"(hi), "f"(lo));
    return r;
}
// convert float4 -> hi/lo bf16x2 words and store to smem
__device__ __forceinline__ void store_hilo(char* sm, unsigned ah_off, unsigned al_off,
                                           unsigned boff, float4 a) {
    unsigned hw0 = bf16x2_rn(a.x, a.y);
    unsigned hw1 = bf16x2_rn(a.z, a.w);
    float h0 = __uint_as_float(hw0 << 16);
    float h1 = __uint_as_float(hw0 & 0xFFFF0000u);
    float h2 = __uint_as_float(hw1 << 16);
    float h3 = __uint_as_float(hw1 & 0xFFFF0000u);
    unsigned lw0 = bf16x2_rn(a.x - h0, a.y - h1);
    unsigned lw1 = bf16x2_rn(a.z - h2, a.w - h3);
    *(unsigned*)(sm + ah_off + boff)     = hw0;
    *(unsigned*)(sm + ah_off + boff + 4) = hw1;
    *(unsigned*)(sm + al_off + boff)     = lw0;
    *(unsigned*)(sm + al_off + boff + 4) = lw1;
}

// ---------------- transpose: NCHW halves -> NHWC concat ----------------
__global__ __launch_bounds__(256)
void transpose_kernel(const float* __restrict__ pB, const float* __restrict__ pA)
{
    __shared__ float tile[64][65];
    int b  = blockIdx.y;
    int s0 = blockIdx.x * 64;
    int t  = threadIdx.x;
    for (int i = t; i < 64 * 64; i += 256) {
        int c = i >> 6, px = i & 63;
        const float* src = (c < 32) ? (pB + ((long)b * 32 + c) * HWS)
                                    : (pA + ((long)b * 32 + (c - 32)) * HWS);
        tile[px][c] = __ldg(src + s0 + px);
    }
    __syncthreads();
    for (int i = t; i < 64 * 64; i += 256) {
        int px = i >> 6, c = i & 63;
        g_x1t[((long)b * HWS + s0 + px) * CC + c] = tile[px][c];
    }
}

// ---------------- prep (weights only) ----------------
__global__ void prep_kernel(
    const float* __restrict__ wo1,
    const float* __restrict__ w1, const float* __restrict__ g1,
    const float* __restrict__ be1, const float* __restrict__ rm1, const float* __restrict__ rv1,
    const float* __restrict__ wo2,
    const float* __restrict__ w2, const float* __restrict__ g2,
    const float* __restrict__ be2, const float* __restrict__ rm2, const float* __restrict__ rv2)
{
    int t = blockIdx.x * blockDim.x + threadIdx.x;
    int stride = gridDim.x * blockDim.x;

    for (int i = t; i < 9 * O1 * CC; i += stride) {
        int c = i & 63;
        int o = (i >> 6) & 63;
        int k = i >> 12;
        float inv = g1[o] * rsqrtf(rv1[o] + 1e-5f);
        float v = w1[(o * CC + c) * 9 + k] * inv;
        __nv_bfloat16 hb = __float2bfloat16(v);
        g_w1h[i] = hb;
        g_w1l[i] = __float2bfloat16(v - __bfloat162float(hb));
    }
    for (int i = t; i < 9 * O2 * CC; i += stride) {
        int c = i & 63;
        int o = (i >> 6) & 31;
        int k = i >> 11;
        float inv = g2[o] * rsqrtf(rv2[o] + 1e-5f);
        float v = w2[(o * CC + c) * 9 + k] * inv;
        __nv_bfloat16 hb = __float2bfloat16(v);
        g_w2h[i] = hb;
        g_w2l[i] = __float2bfloat16(v - __bfloat162float(hb));
    }
    for (int i = t; i < 9 * O2 * CC; i += stride) {
        int c = i & 63;
        int o = (i >> 6) & 31;
        int k = i >> 11;
        float v1 = (o < NOFF) ? wo1[(o * CC + c) * 9 + k] : 0.f;
        float v2 = (o < NOFF) ? wo2[(o * CC + c) * 9 + k] : 0.f;
        __nv_bfloat16 h1 = __float2bfloat16(v1);
        __nv_bfloat16 h2 = __float2bfloat16(v2);
        g_o1h[i] = h1; g_o1l[i] = __float2bfloat16(v1 - __bfloat162float(h1));
        g_o2h[i] = h2; g_o2l[i] = __float2bfloat16(v2 - __bfloat162float(h2));
    }
    if (t < O1) { float inv = g1[t] * rsqrtf(rv1[t] + 1e-5f); g_b1[t] = be1[t] - rm1[t] * inv; }
    if (t < O2) { float inv = g2[t] * rsqrtf(rv2[t] + 1e-5f); g_b2[t] = be2[t] - rm2[t] * inv; }
}

// ---------------- offset conv: per-tap staging from NHWC ----------------
__global__ __launch_bounds__(256, 4)
void offconv_kernel(const float* __restrict__ xt,
                    const __nv_bfloat16* __restrict__ wh,
                    const __nv_bfloat16* __restrict__ wl,
                    const float* __restrict__ bias)
{
    extern __shared__ __align__(16) char sm[];
    const unsigned sb = smem_u32(sm);

    const int tid = threadIdx.x;
    const int wid = tid >> 5;
    const int lid = tid & 31;

    const int b  = blockIdx.x >> 7;
    const int h  = blockIdx.x & 127;
    const int sl = h * WW;

    const int p  = tid & 127;
    const int cb = (tid >> 7) * 32;
    const float* xbase = xt + ((long)b * HWS) * CC + cb;

    const int lrow = lid & 15;
    const int lkof = (lid >> 4) * 8;
    const unsigned a_base = sb + ((wid * 16 + lrow) * ST + lkof) * 2;

    float acc[4][4];
#pragma unroll
    for (int i = 0; i < 4; i++)
#pragma unroll
        for (int j = 0; j < 4; j++) acc[i][j] = 0.f;

#pragma unroll 1
    for (int k = 0; k < 9; k++) {
        // ---- stage A from NHWC ----
        {
            int gy = h + k / 3 - 1;
            int gx = p + k % 3 - 1;
            bool ok = (gy >= 0 && gy < HH && gx >= 0 && gx < WW);
            const float4* src = (const float4*)(xbase + (long)(gy * WW + gx) * CC);
#pragma unroll
            for (int j = 0; j < 8; j++) {
                float4 a = ok ? __ldg(src + j) : make_float4(0.f, 0.f, 0.f, 0.f);
                unsigned boff = (unsigned)(p * ST + cb + 4 * j) * 2u;
                store_hilo(sm, OC_AH, OC_AL, boff, a);
            }
        }
        // ---- stage B ----
        {
            const unsigned* shp = (const unsigned*)(wh + k * (O2 * CC));
            const unsigned* slp = (const unsigned*)(wl + k * (O2 * CC));
            for (int i = tid; i < O2 * 32; i += 256) {
                int n = i >> 5, kw = i & 31;
                ((unsigned*)(sm + OC_BH))[n * (ST / 2) + kw] = __ldg(shp + i);
                ((unsigned*)(sm + OC_BL))[n * (ST / 2) + kw] = __ldg(slp + i);
            }
        }
        __syncthreads();

#pragma unroll
        for (int q = 0; q < 4; q++) {
            unsigned ah[4], al[4];
            ldsm4(ah, a_base + OC_AH + q * 32);
            ldsm4(al, a_base + OC_AL + q * 32);
#pragma unroll
            for (int nf = 0; nf < 2; nf++) {
                unsigned bh[4], bl[4];
                unsigned b_base = sb + ((nf * 16 + lrow) * ST + q * 16 + lkof) * 2;
                ldsm4(bh, b_base + OC_BH);
                ldsm4(bl, b_base + OC_BL);
                mma16816(acc[nf * 2],     ah, bh[0], bh[2]);
                mma16816(acc[nf * 2 + 1], ah, bh[1], bh[3]);
                mma16816(acc[nf * 2],     ah, bl[0], bl[2]);
                mma16816(acc[nf * 2 + 1], ah, bl[1], bl[3]);
                mma16816(acc[nf * 2],     al, bh[0], bh[2]);
                mma16816(acc[nf * 2 + 1], al, bh[1], bh[3]);
            }
        }
        __syncthreads();
    }

    // ---- epilogue: g_off NCHW (sigmoid on 18..26) ----
    const int gm = lid >> 2;
    const int gn = (lid & 3) * 2;
    const int g0 = sl + wid * 16 + gm;
    const int g1i = g0 + 8;

#pragma unroll
    for (int nf = 0; nf < 4; nf++) {
        int o = nf * 8 + gn;
#pragma unroll
        for (int e = 0; e < 2; e++) {
            int oo = o + e;
            if (oo < NOFF) {
                float bb = __ldg(bias + oo);
                float v0 = acc[nf][e] + bb;
                float v1 = acc[nf][e + 2] + bb;
                if (oo >= 18) {
                    v0 = 1.f / (1.f + expf(-v0));
                    v1 = 1.f / (1.f + expf(-v1));
                }
                g_off[(b * NOFF + oo) * HWS + g0]  = v0;
                g_off[(b * NOFF + oo) * HWS + g1i] = v1;
            }
        }
    }
}

// ---------------- deform conv: NHWC gather staging + mma bf16x3 ----------------
// MODE 1: bias+relu -> NHWC out ; MODE 2: bias+relu, gate -> NCHW out
template <int N, int MODE>
__global__ __launch_bounds__(256, 3)
void conv_mma_kernel(const float* __restrict__ xt,
                     const __nv_bfloat16* __restrict__ wh,
                     const __nv_bfloat16* __restrict__ wl,
                     const float* __restrict__ bias,
                     float* __restrict__ out,
                     const float* __restrict__ Aatt,
                     const float* __restrict__ Batt)
{
    extern __shared__ __align__(16) char sm[];
    const unsigned sb = smem_u32(sm);

    const int tid = threadIdx.x;
    const int wid = tid >> 5;
    const int lid = tid & 31;

    const int b  = blockIdx.x >> 7;
    const int h  = blockIdx.x & 127;
    const int sl = h * WW;

    float* swt  = (float*)(sm + SM_SWT);
    int*   sidx = (int*)(sm + SM_SIDX);

    const int p  = tid & 127;
    const int cb = (tid >> 7) * 32;
    const float* xbase = xt + ((long)b * HWS) * CC + cb;

    constexpr int NF16 = N / 16;
    float acc[N / 8][4];
#pragma unroll
    for (int i = 0; i < N / 8; i++)
#pragma unroll
        for (int j = 0; j < 4; j++) acc[i][j] = 0.f;

    const int lrow = lid & 15;
    const int lkof = (lid >> 4) * 8;
    const unsigned a_base = sb + ((wid * 16 + lrow) * ST + lkof) * 2;

#pragma unroll 1
    for (int k = 0; k < 9; k++) {
        if (tid < TP) {
            const float* op = g_off + b * NOFF * HWS + sl + tid;
            float dy = op[(2 * k) * HWS];
            float dx = op[(2 * k + 1) * HWS];
            float m  = op[(18 + k) * HWS];       // pre-sigmoided

            float ys = (float)(h + (k / 3 - 1)) + dy;
            float xs = (float)(tid + (k % 3 - 1)) + dx;
            float y0f = floorf(ys), x0f = floorf(xs);
            float fy = ys - y0f, fx = xs - x0f;
            int y0 = (int)y0f, x0 = (int)x0f;
            int y1 = y0 + 1, x1 = x0 + 1;

            float vy0 = (y0 >= 0 && y0 < HH) ? m : 0.f;
            float vy1 = (y1 >= 0 && y1 < HH) ? m : 0.f;
            float vx0 = (x0 >= 0 && x0 < WW) ? 1.f : 0.f;
            float vx1 = (x1 >= 0 && x1 < WW) ? 1.f : 0.f;

            swt[0 * TP + tid] = (1.f - fy) * (1.f - fx) * vy0 * vx0;
            swt[1 * TP + tid] = (1.f - fy) * fx * vy0 * vx1;
            swt[2 * TP + tid] = fy * (1.f - fx) * vy1 * vx0;
            swt[3 * TP + tid] = fy * fx * vy1 * vx1;

            int cy0 = min(max(y0, 0), HH - 1), cy1 = min(max(y1, 0), HH - 1);
            int cx0 = min(max(x0, 0), WW - 1), cx1 = min(max(x1, 0), WW - 1);
            sidx[0 * TP + tid] = cy0 * WW + cx0;
            sidx[1 * TP + tid] = cy0 * WW + cx1;
            sidx[2 * TP + tid] = cy1 * WW + cx0;
            sidx[3 * TP + tid] = cy1 * WW + cx1;
        }
        __syncthreads();

        // ---- stage A: 4-corner NHWC gather, float4-wide ----
        {
            float w00 = swt[p], w01 = swt[TP + p], w10 = swt[2 * TP + p], w11 = swt[3 * TP + p];
            const float4* c00 = (const float4*)(xbase + (long)sidx[p] * CC);
            const float4* c01 = (const float4*)(xbase + (long)sidx[TP + p] * CC);
            const float4* c10 = (const float4*)(xbase + (long)sidx[2 * TP + p] * CC);
            const float4* c11 = (const float4*)(xbase + (long)sidx[3 * TP + p] * CC);
#pragma unroll
            for (int j = 0; j < 8; j++) {
                float4 a0 = __ldg(c00 + j);
                float4 a1 = __ldg(c01 + j);
                float4 a2 = __ldg(c10 + j);
                float4 a3 = __ldg(c11 + j);
                float4 v;
                v.x = w00 * a0.x + w01 * a1.x + w10 * a2.x + w11 * a3.x;
                v.y = w00 * a0.y + w01 * a1.y + w10 * a2.y + w11 * a3.y;
                v.z = w00 * a0.z + w01 * a1.z + w10 * a2.z + w11 * a3.z;
                v.w = w00 * a0.w + w01 * a1.w + w10 * a2.w + w11 * a3.w;
                unsigned boff = (unsigned)(p * ST + cb + 4 * j) * 2u;
                store_hilo(sm, SM_AH, SM_AL, boff, v);
            }
        }

        // ---- stage B ----
        {
            const unsigned* shp = (const unsigned*)(wh + k * (N * CC));
            const unsigned* slp = (const unsigned*)(wl + k * (N * CC));
            for (int i = tid; i < N * 32; i += 256) {
                int n = i >> 5, kw = i & 31;
                ((unsigned*)(sm + SM_BH))[n * (ST / 2) + kw] = __ldg(shp + i);
                ((unsigned*)(sm + SM_BL))[n * (ST / 2) + kw] = __ldg(slp + i);
            }
        }
        __syncthreads();

#pragma unroll
        for (int q = 0; q < 4; q++) {
            unsigned ah[4], al[4];
            ldsm4(ah, a_base + SM_AH + q * 32);
            ldsm4(al, a_base + SM_AL + q * 32);
#pragma unroll
            for (int nf = 0; nf < NF16; nf++) {
                unsigned bh[4], bl[4];
                unsigned b_base = sb + ((nf * 16 + lrow) * ST + q * 16 + lkof) * 2;
                ldsm4(bh, b_base + SM_BH);
                ldsm4(bl, b_base + SM_BL);
                mma16816(acc[nf * 2],     ah, bh[0], bh[2]);
                mma16816(acc[nf * 2 + 1], ah, bh[1], bh[3]);
                mma16816(acc[nf * 2],     ah, bl[0], bl[2]);
                mma16816(acc[nf * 2 + 1], ah, bl[1], bl[3]);
                mma16816(acc[nf * 2],     al, bh[0], bh[2]);
                mma16816(acc[nf * 2 + 1], al, bh[1], bh[3]);
            }
        }
        __syncthreads();
    }

    // ---- epilogue ----
    const int gm = lid >> 2;
    const int gn = (lid & 3) * 2;
    const int g0 = sl + wid * 16 + gm;
    const int g1i = g0 + 8;

    float ga0 = 1.f, ga1 = 1.f;
    if (MODE == 2) {
        ga0 = (1.f - __ldg(Aatt + b * HWS + g0)) * __ldg(Batt + b * HWS + g0);
        ga1 = (1.f - __ldg(Aatt + b * HWS + g1i)) * __ldg(Batt + b * HWS + g1i);
    }

#pragma unroll
    for (int nf = 0; nf < N / 8; nf++) {
        int o = nf * 8 + gn;
#pragma unroll
        for (int e = 0; e < 2; e++) {
            int oo = o + e;
            float bb = __ldg(bias + oo);
            float v0 = fmaxf(acc[nf][e] + bb, 0.f);
            float v1 = fmaxf(acc[nf][e + 2] + bb, 0.f);
            if (MODE == 1) {
                // NHWC out
                out[((long)b * HWS + g0) * CC + oo]  = v0;
                out[((long)b * HWS + g1i) * CC + oo] = v1;
            } else {
                v0 *= ga0; v1 *= ga1;
                out[(b * N + oo) * HWS + g0]  = v0;
                out[(b * N + oo) * HWS + g1i] = v1;
            }
        }
    }
}

// ---------------- launch ----------------
extern "C" void kernel_launch(void* const* d_in, const int* in_sizes, int n_in,
                              void* d_out, int out_size)
{
    const float* pA   = (const float*)d_in[1];
    const float* pB   = (const float*)d_in[2];
    const float* Aatt = (const float*)d_in[3];
    const float* Batt = (const float*)d_in[4];
    const float* wo1  = (const float*)d_in[5];
    const float* bo1  = (const float*)d_in[6];
    const float* w1   = (const float*)d_in[7];
    const float* g1   = (const float*)d_in[8];
    const float* be1  = (const float*)d_in[9];
    const float* rm1  = (const float*)d_in[10];
    const float* rv1  = (const float*)d_in[11];
    const float* wo2  = (const float*)d_in[12];
    const float* bo2  = (const float*)d_in[13];
    const float* w2   = (const float*)d_in[14];
    const float* g2   = (const float*)d_in[15];
    const float* be2  = (const float*)d_in[16];
    const float* rm2  = (const float*)d_in[17];
    const float* rv2  = (const float*)d_in[18];

    float *x1t, *x2t, *pb1, *pb2;
    __nv_bfloat16 *w1h, *w1l, *w2h, *w2l, *o1h, *o1l, *o2h, *o2l;
    cudaGetSymbolAddress((void**)&x1t, g_x1t);
    cudaGetSymbolAddress((void**)&x2t, g_x2t);
    cudaGetSymbolAddress((void**)&pb1, g_b1);
    cudaGetSymbolAddress((void**)&pb2, g_b2);
    cudaGetSymbolAddress((void**)&w1h, g_w1h);
    cudaGetSymbolAddress((void**)&w1l, g_w1l);
    cudaGetSymbolAddress((void**)&w2h, g_w2h);
    cudaGetSymbolAddress((void**)&w2l, g_w2l);
    cudaGetSymbolAddress((void**)&o1h, g_o1h);
    cudaGetSymbolAddress((void**)&o1l, g_o1l);
    cudaGetSymbolAddress((void**)&o2h, g_o2h);
    cudaGetSymbolAddress((void**)&o2l, g_o2l);

    cudaFuncSetAttribute(offconv_kernel, cudaFuncAttributeMaxDynamicSharedMemorySize, OC_TOT);
    cudaFuncSetAttribute(conv_mma_kernel<64, 1>, cudaFuncAttributeMaxDynamicSharedMemorySize, SM_TOTAL);
    cudaFuncSetAttribute(conv_mma_kernel<32, 2>, cudaFuncAttributeMaxDynamicSharedMemorySize, SM_TOTAL);

    dim3 blk(256);
    dim3 grd(NPIX / TP);   // 512

    prep_kernel<<<64, 256>>>(wo1, w1, g1, be1, rm1, rv1,
                             wo2, w2, g2, be2, rm2, rv2);
    transpose_kernel<<<dim3(HWS / 64, BN), 256>>>(pB, pA);

    offconv_kernel<<<grd, blk, OC_TOT>>>(x1t, o1h, o1l, bo1);
    conv_mma_kernel<64, 1><<<grd, blk, SM_TOTAL>>>(x1t, w1h, w1l, pb1, x2t, nullptr, nullptr);
    offconv_kernel<<<grd, blk, OC_TOT>>>(x2t, o2h, o2l, bo2);
    conv_mma_kernel<32, 2><<<grd, blk, SM_TOTAL>>>(x2t, w2h, w2l, pb2, (float*)d_out, Aatt, Batt);
}

// round 9
// speedup vs baseline: 2.0676x; 2.0676x over previous
#include <cuda_runtime.h>
#include <cuda_bf16.h>
#include <math.h>
#include <stdint.h>

#define BN 4
#define HH 128
#define WW 128
#define HWS (HH * WW)
#define CC 64
#define O1 64
#define O2 32
#define NOFF 27
#define NPIX (BN * HWS)
#define TP 128
#define ST 72              // smem row stride in bf16 elems (144B)

// smem offsets (A hi/lo + B hi/lo)
#define SM_AH   0
#define SM_AL   18432
#define SM_BH   36864
#define SM_BL   46080      // N=64 ends at 55296; N=32 ends at 50688
#define SM_TOT64 55296
#define SM_TOT32 50688

// ---------------- device scratch ----------------
__device__ float g_x2[BN * CC * HWS];
__device__ float g_off[BN * NOFF * HWS];
__device__ __nv_bfloat16 g_w1h[9 * O1 * CC];
__device__ __nv_bfloat16 g_w1l[9 * O1 * CC];
__device__ __nv_bfloat16 g_w2h[9 * O2 * CC];
__device__ __nv_bfloat16 g_w2l[9 * O2 * CC];
__device__ __nv_bfloat16 g_o1h[9 * O2 * CC];
__device__ __nv_bfloat16 g_o1l[9 * O2 * CC];
__device__ __nv_bfloat16 g_o2h[9 * O2 * CC];
__device__ __nv_bfloat16 g_o2l[9 * O2 * CC];
__device__ float g_b1[O1];
__device__ float g_b2[O2];

// ---------------- helpers ----------------
__device__ __forceinline__ unsigned smem_u32(const void* p) {
    unsigned a;
    asm("{ .reg .u64 t; cvta.to.shared.u64 t, %1; cvt.u32.u64 %0, t; }" : "=r"(a) : "l"(p));
    return a;
}
__device__ __forceinline__ void ldsm4(unsigned* r, unsigned addr) {
    asm volatile("ldmatrix.sync.aligned.m8n8.x4.shared.b16 {%0,%1,%2,%3}, [%4];"
                 : "=r"(r[0]), "=r"(r[1]), "=r"(r[2]), "=r"(r[3]) : "r"(addr));
}
__device__ __forceinline__ void mma16816(float* c, const unsigned* a, unsigned b0, unsigned b1) {
    asm volatile(
        "mma.sync.aligned.m16n8k16.row.col.f32.bf16.bf16.f32 "
        "{%0,%1,%2,%3}, {%4,%5,%6,%7}, {%8,%9}, {%0,%1,%2,%3};"
        : "+f"(c[0]), "+f"(c[1]), "+f"(c[2]), "+f"(c[3])
        : "r"(a[0]), "r"(a[1]), "r"(a[2]), "r"(a[3]), "r"(b0), "r"(b1));
}
__device__ __forceinline__ unsigned bf16x2_rn(float lo, float hi) {
    unsigned r;
    asm("cvt.rn.bf16x2.f32 %0, %1, %2;" : "=r"(r) : "f"(hi), "f"(lo));
    return r;
}
__device__ __forceinline__ void cvt_hilo(float v0, float v1, unsigned& hw, unsigned& lw) {
    hw = bf16x2_rn(v0, v1);
    float h0 = __uint_as_float(hw << 16);
    float h1 = __uint_as_float(hw & 0xFFFF0000u);
    lw = bf16x2_rn(v0 - h0, v1 - h1);
}

// ---------------- prep (weights only) ----------------
__global__ void prep_kernel(
    const float* __restrict__ wo1,
    const float* __restrict__ w1, const float* __restrict__ g1,
    const float* __restrict__ be1, const float* __restrict__ rm1, const float* __restrict__ rv1,
    const float* __restrict__ wo2,
    const float* __restrict__ w2, const float* __restrict__ g2,
    const float* __restrict__ be2, const float* __restrict__ rm2, const float* __restrict__ rv2)
{
    int t = blockIdx.x * blockDim.x + threadIdx.x;
    int stride = gridDim.x * blockDim.x;

    for (int i = t; i < 9 * O1 * CC; i += stride) {
        int c = i & 63;
        int o = (i >> 6) & 63;
        int k = i >> 12;
        float inv = g1[o] * rsqrtf(rv1[o] + 1e-5f);
        float v = w1[(o * CC + c) * 9 + k] * inv;
        __nv_bfloat16 hb = __float2bfloat16(v);
        g_w1h[i] = hb;
        g_w1l[i] = __float2bfloat16(v - __bfloat162float(hb));
    }
    for (int i = t; i < 9 * O2 * CC; i += stride) {
        int c = i & 63;
        int o = (i >> 6) & 31;
        int k = i >> 11;
        float inv = g2[o] * rsqrtf(rv2[o] + 1e-5f);
        float v = w2[(o * CC + c) * 9 + k] * inv;
        __nv_bfloat16 hb = __float2bfloat16(v);
        g_w2h[i] = hb;
        g_w2l[i] = __float2bfloat16(v - __bfloat162float(hb));
    }
    for (int i = t; i < 9 * O2 * CC; i += stride) {
        int c = i & 63;
        int o = (i >> 6) & 31;
        int k = i >> 11;
        float v1 = (o < NOFF) ? wo1[(o * CC + c) * 9 + k] : 0.f;
        float v2 = (o < NOFF) ? wo2[(o * CC + c) * 9 + k] : 0.f;
        __nv_bfloat16 h1 = __float2bfloat16(v1);
        __nv_bfloat16 h2 = __float2bfloat16(v2);
        g_o1h[i] = h1; g_o1l[i] = __float2bfloat16(v1 - __bfloat162float(h1));
        g_o2h[i] = h2; g_o2l[i] = __float2bfloat16(v2 - __bfloat162float(h2));
    }
    if (t < O1) { float inv = g1[t] * rsqrtf(rv1[t] + 1e-5f); g_b1[t] = be1[t] - rm1[t] * inv; }
    if (t < O2) { float inv = g2[t] * rsqrtf(rv2[t] + 1e-5f); g_b2[t] = be2[t] - rm2[t] * inv; }
}

// ---------------- gather one tap into registers (hi/lo bf16x2 words) ----------------
// MODE 0: integer window tap. MODE>0: deform bilinear tap via g_off.
template <int MODE>
__device__ __forceinline__ void gather_tap(
    const float* __restrict__ xc,      // channel-half base [32][HWS]
    const float* __restrict__ offp,    // g_off + b*NOFF*HWS + sl + p   (MODE>0)
    int h, int p, int k,
    unsigned* hw, unsigned* lw)
{
    if (MODE == 0) {
        int gy = h + k / 3 - 1;
        int gx = p + k % 3 - 1;
        bool ok = (gy >= 0 && gy < HH && gx >= 0 && gx < WW);
        const float* src = xc + gy * WW + gx;
#pragma unroll
        for (int j = 0; j < 16; j++) {
            float v0 = ok ? __ldg(src + (2 * j) * HWS) : 0.f;
            float v1 = ok ? __ldg(src + (2 * j + 1) * HWS) : 0.f;
            cvt_hilo(v0, v1, hw[j], lw[j]);
        }
    } else {
        float dy = __ldg(offp + (2 * k) * HWS);
        float dx = __ldg(offp + (2 * k + 1) * HWS);
        float m  = __ldg(offp + (18 + k) * HWS);     // pre-sigmoided

        float ys = (float)(h + (k / 3 - 1)) + dy;
        float xs = (float)(p + (k % 3 - 1)) + dx;
        float y0f = floorf(ys), x0f = floorf(xs);
        float fy = ys - y0f, fx = xs - x0f;
        int y0 = (int)y0f, x0 = (int)x0f;
        int y1 = y0 + 1, x1 = x0 + 1;

        float vy0 = (y0 >= 0 && y0 < HH) ? m : 0.f;
        float vy1 = (y1 >= 0 && y1 < HH) ? m : 0.f;
        float vx0 = (x0 >= 0 && x0 < WW) ? 1.f : 0.f;
        float vx1 = (x1 >= 0 && x1 < WW) ? 1.f : 0.f;

        float w00 = (1.f - fy) * (1.f - fx) * vy0 * vx0;
        float w01 = (1.f - fy) * fx * vy0 * vx1;
        float w10 = fy * (1.f - fx) * vy1 * vx0;
        float w11 = fy * fx * vy1 * vx1;

        int cy0 = min(max(y0, 0), HH - 1), cy1 = min(max(y1, 0), HH - 1);
        int cx0 = min(max(x0, 0), WW - 1), cx1 = min(max(x1, 0), WW - 1);
        int i00 = cy0 * WW + cx0, i01 = cy0 * WW + cx1;
        int i10 = cy1 * WW + cx0, i11 = cy1 * WW + cx1;

#pragma unroll
        for (int j = 0; j < 16; j++) {
            const float* x0p = xc + (2 * j) * HWS;
            const float* x1p = x0p + HWS;
            float v0 = w00 * __ldg(x0p + i00) + w01 * __ldg(x0p + i01)
                     + w10 * __ldg(x0p + i10) + w11 * __ldg(x0p + i11);
            float v1 = w00 * __ldg(x1p + i00) + w01 * __ldg(x1p + i01)
                     + w10 * __ldg(x1p + i10) + w11 * __ldg(x1p + i11);
            cvt_hilo(v0, v1, hw[j], lw[j]);
        }
    }
}

__device__ __forceinline__ void store_tap(char* sm, int p, int cb,
                                          const unsigned* hw, const unsigned* lw)
{
#pragma unroll
    for (int j = 0; j < 8; j++) {
        unsigned boff = (unsigned)(p * ST + cb + 4 * j) * 2u;
        *(uint2*)(sm + SM_AH + boff) = make_uint2(hw[2 * j], hw[2 * j + 1]);
        *(uint2*)(sm + SM_AL + boff) = make_uint2(lw[2 * j], lw[2 * j + 1]);
    }
}

// ---------------- fused conv, software-pipelined ----------------
// MODE 0: offset conv -> g_off (bias, sigmoid 18..26)
// MODE 1: deform conv -> bias+relu (NCHW out)
// MODE 2: deform conv -> bias+relu, *(1-Aatt)*Batt
template <int N, int MODE, int MINB>
__global__ __launch_bounds__(256, MINB)
void conv_mma_kernel(const float* __restrict__ xA, const float* __restrict__ xB,
                     long bstr,
                     const __nv_bfloat16* __restrict__ wh,
                     const __nv_bfloat16* __restrict__ wl,
                     const float* __restrict__ bias,
                     float* __restrict__ out,
                     const float* __restrict__ Aatt,
                     const float* __restrict__ Batt)
{
    extern __shared__ __align__(16) char sm[];
    const unsigned sb = smem_u32(sm);

    const int tid = threadIdx.x;
    const int wid = tid >> 5;
    const int lid = tid & 31;

    const int b  = blockIdx.x >> 7;
    const int h  = blockIdx.x & 127;
    const int sl = h * WW;

    const int p  = tid & 127;
    const int cb = (tid >> 7) * 32;
    const float* xc = ((tid >> 7) == 0) ? (xA + b * bstr) : (xB + b * bstr);
    const float* offp = g_off + b * NOFF * HWS + sl + p;

    constexpr int NF16 = N / 16;
    constexpr int NBI  = (N * 32) / 256;      // B words per thread (8 or 4)

    float acc[N / 8][4];
#pragma unroll
    for (int i = 0; i < N / 8; i++)
#pragma unroll
        for (int j = 0; j < 4; j++) acc[i][j] = 0.f;

    const int lrow = lid & 15;
    const int lkof = (lid >> 4) * 8;
    const unsigned a_base = sb + ((wid * 16 + lrow) * ST + lkof) * 2;

    unsigned hw[16], lw[16];
    unsigned rbh[NBI], rbl[NBI];

    // ---- prologue: stage tap 0 ----
    gather_tap<MODE>(xc, offp, h, p, 0, hw, lw);
    {
        const unsigned* shp = (const unsigned*)wh;
        const unsigned* slp = (const unsigned*)wl;
#pragma unroll
        for (int t2 = 0; t2 < NBI; t2++) {
            rbh[t2] = __ldg(shp + tid + t2 * 256);
            rbl[t2] = __ldg(slp + tid + t2 * 256);
        }
    }
    store_tap(sm, p, cb, hw, lw);
#pragma unroll
    for (int t2 = 0; t2 < NBI; t2++) {
        int i = tid + t2 * 256;
        int n = i >> 5, kw = i & 31;
        ((unsigned*)(sm + SM_BH))[n * (ST / 2) + kw] = rbh[t2];
        ((unsigned*)(sm + SM_BL))[n * (ST / 2) + kw] = rbl[t2];
    }
    __syncthreads();

#pragma unroll 1
    for (int k = 0; k < 9; k++) {
        // ---- prefetch tap k+1 into registers ----
        if (k < 8) {
            gather_tap<MODE>(xc, offp, h, p, k + 1, hw, lw);
            const unsigned* shp = (const unsigned*)(wh + (k + 1) * (N * CC));
            const unsigned* slp = (const unsigned*)(wl + (k + 1) * (N * CC));
#pragma unroll
            for (int t2 = 0; t2 < NBI; t2++) {
                rbh[t2] = __ldg(shp + tid + t2 * 256);
                rbl[t2] = __ldg(slp + tid + t2 * 256);
            }
        }

        // ---- MMA tap k from smem ----
#pragma unroll
        for (int q = 0; q < 4; q++) {
            unsigned ah[4], al[4];
            ldsm4(ah, a_base + SM_AH + q * 32);
            ldsm4(al, a_base + SM_AL + q * 32);
#pragma unroll
            for (int nf = 0; nf < NF16; nf++) {
                unsigned bh[4], bl[4];
                unsigned b_base = sb + ((nf * 16 + lrow) * ST + q * 16 + lkof) * 2;
                ldsm4(bh, b_base + SM_BH);
                ldsm4(bl, b_base + SM_BL);
                mma16816(acc[nf * 2],     ah, bh[0], bh[2]);
                mma16816(acc[nf * 2 + 1], ah, bh[1], bh[3]);
                mma16816(acc[nf * 2],     ah, bl[0], bl[2]);
                mma16816(acc[nf * 2 + 1], ah, bl[1], bl[3]);
                mma16816(acc[nf * 2],     al, bh[0], bh[2]);
                mma16816(acc[nf * 2 + 1], al, bh[1], bh[3]);
            }
        }
        __syncthreads();

        // ---- store tap k+1 ----
        if (k < 8) {
            store_tap(sm, p, cb, hw, lw);
#pragma unroll
            for (int t2 = 0; t2 < NBI; t2++) {
                int i = tid + t2 * 256;
                int n = i >> 5, kw = i & 31;
                ((unsigned*)(sm + SM_BH))[n * (ST / 2) + kw] = rbh[t2];
                ((unsigned*)(sm + SM_BL))[n * (ST / 2) + kw] = rbl[t2];
            }
            __syncthreads();
        }
    }

    // ---- epilogue ----
    const int gm = lid >> 2;
    const int gn = (lid & 3) * 2;
    const int g0 = sl + wid * 16 + gm;
    const int g1i = g0 + 8;

    float ga0 = 1.f, ga1 = 1.f;
    if (MODE == 2) {
        ga0 = (1.f - __ldg(Aatt + b * HWS + g0)) * __ldg(Batt + b * HWS + g0);
        ga1 = (1.f - __ldg(Aatt + b * HWS + g1i)) * __ldg(Batt + b * HWS + g1i);
    }

#pragma unroll
    for (int nf = 0; nf < N / 8; nf++) {
        int o = nf * 8 + gn;
#pragma unroll
        for (int e = 0; e < 2; e++) {
            int oo = o + e;
            float v0 = acc[nf][e];
            float v1 = acc[nf][e + 2];
            if (MODE == 0) {
                if (oo < NOFF) {
                    float bb = __ldg(bias + oo);
                    v0 += bb; v1 += bb;
                    if (oo >= 18) {
                        v0 = 1.f / (1.f + expf(-v0));
                        v1 = 1.f / (1.f + expf(-v1));
                    }
                    out[(b * NOFF + oo) * HWS + g0]  = v0;
                    out[(b * NOFF + oo) * HWS + g1i] = v1;
                }
            } else {
                float bb = __ldg(bias + oo);
                v0 = fmaxf(v0 + bb, 0.f);
                v1 = fmaxf(v1 + bb, 0.f);
                if (MODE == 2) { v0 *= ga0; v1 *= ga1; }
                out[(b * N + oo) * HWS + g0]  = v0;
                out[(b * N + oo) * HWS + g1i] = v1;
            }
        }
    }
}

// ---------------- launch ----------------
extern "C" void kernel_launch(void* const* d_in, const int* in_sizes, int n_in,
                              void* d_out, int out_size)
{
    const float* pA   = (const float*)d_in[1];
    const float* pB   = (const float*)d_in[2];
    const float* Aatt = (const float*)d_in[3];
    const float* Batt = (const float*)d_in[4];
    const float* wo1  = (const float*)d_in[5];
    const float* bo1  = (const float*)d_in[6];
    const float* w1   = (const float*)d_in[7];
    const float* g1   = (const float*)d_in[8];
    const float* be1  = (const float*)d_in[9];
    const float* rm1  = (const float*)d_in[10];
    const float* rv1  = (const float*)d_in[11];
    const float* wo2  = (const float*)d_in[12];
    const float* bo2  = (const float*)d_in[13];
    const float* w2   = (const float*)d_in[14];
    const float* g2   = (const float*)d_in[15];
    const float* be2  = (const float*)d_in[16];
    const float* rm2  = (const float*)d_in[17];
    const float* rv2  = (const float*)d_in[18];

    float *x2, *off, *pb1, *pb2;
    __nv_bfloat16 *w1h, *w1l, *w2h, *w2l, *o1h, *o1l, *o2h, *o2l;
    cudaGetSymbolAddress((void**)&x2,  g_x2);
    cudaGetSymbolAddress((void**)&off, g_off);
    cudaGetSymbolAddress((void**)&pb1, g_b1);
    cudaGetSymbolAddress((void**)&pb2, g_b2);
    cudaGetSymbolAddress((void**)&w1h, g_w1h);
    cudaGetSymbolAddress((void**)&w1l, g_w1l);
    cudaGetSymbolAddress((void**)&w2h, g_w2h);
    cudaGetSymbolAddress((void**)&w2l, g_w2l);
    cudaGetSymbolAddress((void**)&o1h, g_o1h);
    cudaGetSymbolAddress((void**)&o1l, g_o1l);
    cudaGetSymbolAddress((void**)&o2h, g_o2h);
    cudaGetSymbolAddress((void**)&o2l, g_o2l);

    cudaFuncSetAttribute(conv_mma_kernel<32, 0, 3>, cudaFuncAttributeMaxDynamicSharedMemorySize, SM_TOT32);
    cudaFuncSetAttribute(conv_mma_kernel<64, 1, 2>, cudaFuncAttributeMaxDynamicSharedMemorySize, SM_TOT64);
    cudaFuncSetAttribute(conv_mma_kernel<32, 2, 3>, cudaFuncAttributeMaxDynamicSharedMemorySize, SM_TOT32);

    dim3 blk(256);
    dim3 grd(NPIX / TP);   // 512
    const long s32 = 32L * HWS;
    const long s64 = 64L * HWS;

    prep_kernel<<<64, 256>>>(wo1, w1, g1, be1, rm1, rv1,
                             wo2, w2, g2, be2, rm2, rv2);

    conv_mma_kernel<32, 0, 3><<<grd, blk, SM_TOT32>>>(pB, pA, s32, o1h, o1l, bo1, off, nullptr, nullptr);
    conv_mma_kernel<64, 1, 2><<<grd, blk, SM_TOT64>>>(pB, pA, s32, w1h, w1l, pb1, x2, nullptr, nullptr);
    conv_mma_kernel<32, 0, 3><<<grd, blk, SM_TOT32>>>(x2, x2 + 32 * HWS, s64, o2h, o2l, bo2, off, nullptr, nullptr);
    conv_mma_kernel<32, 2, 3><<<grd, blk, SM_TOT32>>>(x2, x2 + 32 * HWS, s64, w2h, w2l, pb2,
                                                      (float*)d_out, Aatt, Batt);
}

// round 10
// speedup vs baseline: 2.1148x; 1.0228x over previous
#include <cuda_runtime.h>
#include <cuda_bf16.h>
#include <math.h>
#include <stdint.h>

#define BN 4
#define HH 128
#define WW 128
#define HWS (HH * WW)
#define CC 64
#define O1 64
#define O2 32
#define NOFF 27
#define NPIX (BN * HWS)
#define TP 128
#define ST 72              // smem row stride in bf16 elems (144B)

#define SM_AH   0
#define SM_AL   18432
#define SM_BH   36864      // B hi at 36864, sized NMAIN*144

// ---------------- device scratch ----------------
__device__ float g_x2[BN * CC * HWS];
__device__ __nv_bfloat16 g_w1h[9 * O1 * CC];
__device__ __nv_bfloat16 g_w1l[9 * O1 * CC];
__device__ __nv_bfloat16 g_w2h[9 * O2 * CC];
__device__ __nv_bfloat16 g_w2l[9 * O2 * CC];
__device__ __nv_bfloat16 g_o1h[9 * O2 * CC];
__device__ __nv_bfloat16 g_o1l[9 * O2 * CC];
__device__ __nv_bfloat16 g_o2h[9 * O2 * CC];
__device__ __nv_bfloat16 g_o2l[9 * O2 * CC];
__device__ float g_b1[O1];
__device__ float g_b2[O2];

// ---------------- helpers ----------------
__device__ __forceinline__ unsigned smem_u32(const void* p) {
    unsigned a;
    asm("{ .reg .u64 t; cvta.to.shared.u64 t, %1; cvt.u32.u64 %0, t; }" : "=r"(a) : "l"(p));
    return a;
}
__device__ __forceinline__ void ldsm4(unsigned* r, unsigned addr) {
    asm volatile("ldmatrix.sync.aligned.m8n8.x4.shared.b16 {%0,%1,%2,%3}, [%4];"
                 : "=r"(r[0]), "=r"(r[1]), "=r"(r[2]), "=r"(r[3]) : "r"(addr));
}
__device__ __forceinline__ void mma16816(float* c, const unsigned* a, unsigned b0, unsigned b1) {
    asm volatile(
        "mma.sync.aligned.m16n8k16.row.col.f32.bf16.bf16.f32 "
        "{%0,%1,%2,%3}, {%4,%5,%6,%7}, {%8,%9}, {%0,%1,%2,%3};"
        : "+f"(c[0]), "+f"(c[1]), "+f"(c[2]), "+f"(c[3])
        : "r"(a[0]), "r"(a[1]), "r"(a[2]), "r"(a[3]), "r"(b0), "r"(b1));
}
__device__ __forceinline__ unsigned bf16x2_rn(float lo, float hi) {
    unsigned r;
    asm("cvt.rn.bf16x2.f32 %0, %1, %2;" : "=r"(r) : "f"(hi), "f"(lo));
    return r;
}
__device__ __forceinline__ void cvt_hilo(float v0, float v1, unsigned& hw, unsigned& lw) {
    hw = bf16x2_rn(v0, v1);
    float h0 = __uint_as_float(hw << 16);
    float h1 = __uint_as_float(hw & 0xFFFF0000u);
    lw = bf16x2_rn(v0 - h0, v1 - h1);
}

// ---------------- prep (weights only) ----------------
__global__ void prep_kernel(
    const float* __restrict__ wo1,
    const float* __restrict__ w1, const float* __restrict__ g1,
    const float* __restrict__ be1, const float* __restrict__ rm1, const float* __restrict__ rv1,
    const float* __restrict__ wo2,
    const float* __restrict__ w2, const float* __restrict__ g2,
    const float* __restrict__ be2, const float* __restrict__ rm2, const float* __restrict__ rv2)
{
    int t = blockIdx.x * blockDim.x + threadIdx.x;
    int stride = gridDim.x * blockDim.x;

    for (int i = t; i < 9 * O1 * CC; i += stride) {
        int c = i & 63;
        int o = (i >> 6) & 63;
        int k = i >> 12;
        float inv = g1[o] * rsqrtf(rv1[o] + 1e-5f);
        float v = w1[(o * CC + c) * 9 + k] * inv;
        __nv_bfloat16 hb = __float2bfloat16(v);
        g_w1h[i] = hb;
        g_w1l[i] = __float2bfloat16(v - __bfloat162float(hb));
    }
    for (int i = t; i < 9 * O2 * CC; i += stride) {
        int c = i & 63;
        int o = (i >> 6) & 31;
        int k = i >> 11;
        float inv = g2[o] * rsqrtf(rv2[o] + 1e-5f);
        float v = w2[(o * CC + c) * 9 + k] * inv;
        __nv_bfloat16 hb = __float2bfloat16(v);
        g_w2h[i] = hb;
        g_w2l[i] = __float2bfloat16(v - __bfloat162float(hb));
    }
    for (int i = t; i < 9 * O2 * CC; i += stride) {
        int c = i & 63;
        int o = (i >> 6) & 31;
        int k = i >> 11;
        float v1 = (o < NOFF) ? wo1[(o * CC + c) * 9 + k] : 0.f;
        float v2 = (o < NOFF) ? wo2[(o * CC + c) * 9 + k] : 0.f;
        __nv_bfloat16 h1 = __float2bfloat16(v1);
        __nv_bfloat16 h2 = __float2bfloat16(v2);
        g_o1h[i] = h1; g_o1l[i] = __float2bfloat16(v1 - __bfloat162float(h1));
        g_o2h[i] = h2; g_o2l[i] = __float2bfloat16(v2 - __bfloat162float(h2));
    }
    if (t < O1) { float inv = g1[t] * rsqrtf(rv1[t] + 1e-5f); g_b1[t] = be1[t] - rm1[t] * inv; }
    if (t < O2) { float inv = g2[t] * rsqrtf(rv2[t] + 1e-5f); g_b2[t] = be2[t] - rm2[t] * inv; }
}

// ---------------- gather one tap into registers ----------------
// MODE 0: integer tap. MODE>0: bilinear tap, offsets from smem soff[o][128].
template <int MODE>
__device__ __forceinline__ void gather_tap(
    const float* __restrict__ xc, const float* __restrict__ soff,
    int h, int p, int k,
    unsigned* hw, unsigned* lw)
{
    if (MODE == 0) {
        int gy = h + k / 3 - 1;
        int gx = p + k % 3 - 1;
        bool ok = (gy >= 0 && gy < HH && gx >= 0 && gx < WW);
        const float* src = xc + gy * WW + gx;
#pragma unroll
        for (int j = 0; j < 16; j++) {
            float v0 = ok ? __ldg(src + (2 * j) * HWS) : 0.f;
            float v1 = ok ? __ldg(src + (2 * j + 1) * HWS) : 0.f;
            cvt_hilo(v0, v1, hw[j], lw[j]);
        }
    } else {
        float dy = soff[(2 * k) * TP + p];
        float dx = soff[(2 * k + 1) * TP + p];
        float m  = soff[(18 + k) * TP + p];      // pre-sigmoided

        float ys = (float)(h + (k / 3 - 1)) + dy;
        float xs = (float)(p + (k % 3 - 1)) + dx;
        float y0f = floorf(ys), x0f = floorf(xs);
        float fy = ys - y0f, fx = xs - x0f;
        int y0 = (int)y0f, x0 = (int)x0f;
        int y1 = y0 + 1, x1 = x0 + 1;

        float vy0 = (y0 >= 0 && y0 < HH) ? m : 0.f;
        float vy1 = (y1 >= 0 && y1 < HH) ? m : 0.f;
        float vx0 = (x0 >= 0 && x0 < WW) ? 1.f : 0.f;
        float vx1 = (x1 >= 0 && x1 < WW) ? 1.f : 0.f;

        float w00 = (1.f - fy) * (1.f - fx) * vy0 * vx0;
        float w01 = (1.f - fy) * fx * vy0 * vx1;
        float w10 = fy * (1.f - fx) * vy1 * vx0;
        float w11 = fy * fx * vy1 * vx1;

        int cy0 = min(max(y0, 0), HH - 1), cy1 = min(max(y1, 0), HH - 1);
        int cx0 = min(max(x0, 0), WW - 1), cx1 = min(max(x1, 0), WW - 1);
        int i00 = cy0 * WW + cx0, i01 = cy0 * WW + cx1;
        int i10 = cy1 * WW + cx0, i11 = cy1 * WW + cx1;

#pragma unroll
        for (int j = 0; j < 16; j++) {
            const float* x0p = xc + (2 * j) * HWS;
            const float* x1p = x0p + HWS;
            float v0 = w00 * __ldg(x0p + i00) + w01 * __ldg(x0p + i01)
                     + w10 * __ldg(x0p + i10) + w11 * __ldg(x0p + i11);
            float v1 = w00 * __ldg(x1p + i00) + w01 * __ldg(x1p + i01)
                     + w10 * __ldg(x1p + i10) + w11 * __ldg(x1p + i11);
            cvt_hilo(v0, v1, hw[j], lw[j]);
        }
    }
}

__device__ __forceinline__ void store_tap(char* sm, int p, int cb,
                                          const unsigned* hw, const unsigned* lw)
{
#pragma unroll
    for (int j = 0; j < 8; j++) {
        unsigned boff = (unsigned)(p * ST + cb + 4 * j) * 2u;
        *(uint2*)(sm + SM_AH + boff) = make_uint2(hw[2 * j], hw[2 * j + 1]);
        *(uint2*)(sm + SM_AL + boff) = make_uint2(lw[2 * j], lw[2 * j + 1]);
    }
}

// ---------------- pipelined conv phase (9 taps, bf16x3 MMA) ----------------
template <int N, int MODE>
__device__ __forceinline__ void run_conv(
    char* sm, unsigned sb, unsigned smBH, unsigned smBL,
    const float* __restrict__ xc, const float* __restrict__ soff,
    const __nv_bfloat16* __restrict__ wh, const __nv_bfloat16* __restrict__ wl,
    int h, int p, int cb, int tid, int wid, int lid,
    float (&acc)[N / 8][4])
{
    constexpr int NF16 = N / 16;
    constexpr int NBI  = (N * 32) / 256;

    const int lrow = lid & 15;
    const int lkof = (lid >> 4) * 8;
    const unsigned a_base = sb + ((wid * 16 + lrow) * ST + lkof) * 2;

    unsigned hw[16], lw[16];
    unsigned rbh[NBI], rbl[NBI];

    gather_tap<MODE>(xc, soff, h, p, 0, hw, lw);
    {
        const unsigned* shp = (const unsigned*)wh;
        const unsigned* slp = (const unsigned*)wl;
#pragma unroll
        for (int t2 = 0; t2 < NBI; t2++) {
            rbh[t2] = __ldg(shp + tid + t2 * 256);
            rbl[t2] = __ldg(slp + tid + t2 * 256);
        }
    }
    store_tap(sm, p, cb, hw, lw);
#pragma unroll
    for (int t2 = 0; t2 < NBI; t2++) {
        int i = tid + t2 * 256;
        int n = i >> 5, kw = i & 31;
        ((unsigned*)(sm + smBH))[n * (ST / 2) + kw] = rbh[t2];
        ((unsigned*)(sm + smBL))[n * (ST / 2) + kw] = rbl[t2];
    }
    __syncthreads();

#pragma unroll 1
    for (int k = 0; k < 9; k++) {
        if (k < 8) {
            gather_tap<MODE>(xc, soff, h, p, k + 1, hw, lw);
            const unsigned* shp = (const unsigned*)(wh + (k + 1) * (N * CC));
            const unsigned* slp = (const unsigned*)(wl + (k + 1) * (N * CC));
#pragma unroll
            for (int t2 = 0; t2 < NBI; t2++) {
                rbh[t2] = __ldg(shp + tid + t2 * 256);
                rbl[t2] = __ldg(slp + tid + t2 * 256);
            }
        }

#pragma unroll
        for (int q = 0; q < 4; q++) {
            unsigned ah[4], al[4];
            ldsm4(ah, a_base + SM_AH + q * 32);
            ldsm4(al, a_base + SM_AL + q * 32);
#pragma unroll
            for (int nf = 0; nf < NF16; nf++) {
                unsigned bh[4], bl[4];
                unsigned b_base = sb + ((nf * 16 + lrow) * ST + q * 16 + lkof) * 2;
                ldsm4(bh, b_base + (smBH - 0));
                ldsm4(bl, b_base + (smBL - 0));
                mma16816(acc[nf * 2],     ah, bh[0], bh[2]);
                mma16816(acc[nf * 2 + 1], ah, bh[1], bh[3]);
                mma16816(acc[nf * 2],     ah, bl[0], bl[2]);
                mma16816(acc[nf * 2 + 1], ah, bl[1], bl[3]);
                mma16816(acc[nf * 2],     al, bh[0], bh[2]);
                mma16816(acc[nf * 2 + 1], al, bh[1], bh[3]);
            }
        }
        __syncthreads();

        if (k < 8) {
            store_tap(sm, p, cb, hw, lw);
#pragma unroll
            for (int t2 = 0; t2 < NBI; t2++) {
                int i = tid + t2 * 256;
                int n = i >> 5, kw = i & 31;
                ((unsigned*)(sm + smBH))[n * (ST / 2) + kw] = rbh[t2];
                ((unsigned*)(sm + smBL))[n * (ST / 2) + kw] = rbl[t2];
            }
            __syncthreads();
        }
    }
}

// ---------------- fused layer: offconv -> smem offsets -> deform conv ----------------
// MODE2 1: bias+relu -> NCHW out. MODE2 2: bias+relu, gate -> out.
template <int NMAIN, int MODE2, int MINB>
__global__ __launch_bounds__(256, MINB)
void fused_layer_kernel(const float* __restrict__ xA, const float* __restrict__ xB,
                        long bstr,
                        const __nv_bfloat16* __restrict__ owh, const __nv_bfloat16* __restrict__ owl,
                        const float* __restrict__ obias,
                        const __nv_bfloat16* __restrict__ mwh, const __nv_bfloat16* __restrict__ mwl,
                        const float* __restrict__ mbias,
                        float* __restrict__ out,
                        const float* __restrict__ Aatt, const float* __restrict__ Batt)
{
    extern __shared__ __align__(16) char sm[];
    const unsigned sb = smem_u32(sm);

    constexpr unsigned BSZ    = NMAIN * 144;        // B tile bytes (rows*ST*2)
    constexpr unsigned SM_BL_ = SM_BH + BSZ;
    constexpr unsigned SM_OFF = SM_BL_ + BSZ;

    float* soff = (float*)(sm + SM_OFF);            // [27][128]

    const int tid = threadIdx.x;
    const int wid = tid >> 5;
    const int lid = tid & 31;

    const int b  = blockIdx.x >> 7;
    const int h  = blockIdx.x & 127;
    const int sl = h * WW;

    const int p  = tid & 127;
    const int cb = (tid >> 7) * 32;
    const float* xc = ((tid >> 7) == 0) ? (xA + b * bstr) : (xB + b * bstr);

    const int gm = lid >> 2;
    const int gn = (lid & 3) * 2;
    const int px0 = wid * 16 + gm;
    const int px1 = px0 + 8;

    // ===== phase 1: offset conv (N=32) =====
    {
        float acc[4][4];
#pragma unroll
        for (int i = 0; i < 4; i++)
#pragma unroll
            for (int j = 0; j < 4; j++) acc[i][j] = 0.f;

        run_conv<32, 0>(sm, sb, SM_BH, SM_BL_, xc, nullptr, owh, owl,
                        h, p, cb, tid, wid, lid, acc);

        // epilogue -> smem soff (bias + sigmoid on 18..26)
#pragma unroll
        for (int nf = 0; nf < 4; nf++) {
            int o = nf * 8 + gn;
#pragma unroll
            for (int e = 0; e < 2; e++) {
                int oo = o + e;
                if (oo < NOFF) {
                    float bb = __ldg(obias + oo);
                    float v0 = acc[nf][e] + bb;
                    float v1 = acc[nf][e + 2] + bb;
                    if (oo >= 18) {
                        v0 = 1.f / (1.f + expf(-v0));
                        v1 = 1.f / (1.f + expf(-v1));
                    }
                    soff[oo * TP + px0] = v0;
                    soff[oo * TP + px1] = v1;
                }
            }
        }
        __syncthreads();
    }

    // ===== phase 2: deform conv (N = NMAIN) =====
    {
        float acc[NMAIN / 8][4];
#pragma unroll
        for (int i = 0; i < NMAIN / 8; i++)
#pragma unroll
            for (int j = 0; j < 4; j++) acc[i][j] = 0.f;

        run_conv<NMAIN, 1>(sm, sb, SM_BH, SM_BL_, xc, soff, mwh, mwl,
                           h, p, cb, tid, wid, lid, acc);

        const int g0 = sl + px0;
        const int g1i = sl + px1;

        float ga0 = 1.f, ga1 = 1.f;
        if (MODE2 == 2) {
            ga0 = (1.f - __ldg(Aatt + b * HWS + g0)) * __ldg(Batt + b * HWS + g0);
            ga1 = (1.f - __ldg(Aatt + b * HWS + g1i)) * __ldg(Batt + b * HWS + g1i);
        }

#pragma unroll
        for (int nf = 0; nf < NMAIN / 8; nf++) {
            int o = nf * 8 + gn;
#pragma unroll
            for (int e = 0; e < 2; e++) {
                int oo = o + e;
                float bb = __ldg(mbias + oo);
                float v0 = fmaxf(acc[nf][e] + bb, 0.f);
                float v1 = fmaxf(acc[nf][e + 2] + bb, 0.f);
                if (MODE2 == 2) { v0 *= ga0; v1 *= ga1; }
                out[(b * NMAIN + oo) * HWS + g0]  = v0;
                out[(b * NMAIN + oo) * HWS + g1i] = v1;
            }
        }
    }
}

// ---------------- launch ----------------
extern "C" void kernel_launch(void* const* d_in, const int* in_sizes, int n_in,
                              void* d_out, int out_size)
{
    const float* pA   = (const float*)d_in[1];
    const float* pB   = (const float*)d_in[2];
    const float* Aatt = (const float*)d_in[3];
    const float* Batt = (const float*)d_in[4];
    const float* wo1  = (const float*)d_in[5];
    const float* bo1  = (const float*)d_in[6];
    const float* w1   = (const float*)d_in[7];
    const float* g1   = (const float*)d_in[8];
    const float* be1  = (const float*)d_in[9];
    const float* rm1  = (const float*)d_in[10];
    const float* rv1  = (const float*)d_in[11];
    const float* wo2  = (const float*)d_in[12];
    const float* bo2  = (const float*)d_in[13];
    const float* w2   = (const float*)d_in[14];
    const float* g2   = (const float*)d_in[15];
    const float* be2  = (const float*)d_in[16];
    const float* rm2  = (const float*)d_in[17];
    const float* rv2  = (const float*)d_in[18];

    float *x2, *pb1, *pb2;
    __nv_bfloat16 *w1h, *w1l, *w2h, *w2l, *o1h, *o1l, *o2h, *o2l;
    cudaGetSymbolAddress((void**)&x2,  g_x2);
    cudaGetSymbolAddress((void**)&pb1, g_b1);
    cudaGetSymbolAddress((void**)&pb2, g_b2);
    cudaGetSymbolAddress((void**)&w1h, g_w1h);
    cudaGetSymbolAddress((void**)&w1l, g_w1l);
    cudaGetSymbolAddress((void**)&w2h, g_w2h);
    cudaGetSymbolAddress((void**)&w2l, g_w2l);
    cudaGetSymbolAddress((void**)&o1h, g_o1h);
    cudaGetSymbolAddress((void**)&o1l, g_o1l);
    cudaGetSymbolAddress((void**)&o2h, g_o2h);
    cudaGetSymbolAddress((void**)&o2l, g_o2l);

    const int smem1 = SM_BH + 2 * (O1 * 144) + NOFF * TP * 4;   // 69120
    const int smem2 = SM_BH + 2 * (O2 * 144) + NOFF * TP * 4;   // 59904
    cudaFuncSetAttribute(fused_layer_kernel<O1, 1, 2>, cudaFuncAttributeMaxDynamicSharedMemorySize, smem1);
    cudaFuncSetAttribute(fused_layer_kernel<O2, 2, 3>, cudaFuncAttributeMaxDynamicSharedMemorySize, smem2);

    dim3 blk(256);
    dim3 grd(NPIX / TP);   // 512
    const long s32 = 32L * HWS;
    const long s64 = 64L * HWS;

    prep_kernel<<<64, 256>>>(wo1, w1, g1, be1, rm1, rv1,
                             wo2, w2, g2, be2, rm2, rv2);

    fused_layer_kernel<O1, 1, 2><<<grd, blk, smem1>>>(
        pB, pA, s32, o1h, o1l, bo1, w1h, w1l, pb1, x2, nullptr, nullptr);
    fused_layer_kernel<O2, 2, 3><<<grd, blk, smem2>>>(
        x2, x2 + 32 * HWS, s64, o2h, o2l, bo2, w2h, w2l, pb2,
        (float*)d_out, Aatt, Batt);
}